// round 15
// baseline (speedup 1.0000x reference)
#include <cuda_runtime.h>

#define NPW      2048      // 65536 points / 32 bits (ref bitmask words per scene)
#define STRIDE   65536     // byte-table row stride (= NPW*32)
#define PTOT_MAX 512
#define BMAX     8
#define MAXP     128

__device__ unsigned char      g_pc_bytes[PTOT_MAX * STRIDE]; // 32 MB byte table; zeroed-on-read
__device__ unsigned           g_ref_bits[BMAX * NPW];        // per-scene reference bitmask
__device__ int                g_offs[BMAX + 1];
__device__ unsigned long long g_amax[BMAX];                  // packed (iou<<32 | 0x7fffffff-p)

// ---- Kernel A: scatter (2 pairs/thread, plain byte stores) + ref ballot + offsets + amax reset ----
__global__ void __launch_bounds__(256, 8)
k_main(const int4* __restrict__ pidx2, const int2* __restrict__ pidx,
       const int* __restrict__ labels, const int* __restrict__ object_id,
       const int* __restrict__ pes,
       int M, int M2, int B, int npoint, int n_total, unsigned npu) {
    int t = blockIdx.x * blockDim.x + threadIdx.x;

    if (t == 0) {
        g_offs[0] = 0;
        for (int b = 0; b < B; b++) g_offs[b + 1] = g_offs[b] + __ldg(&pes[b]);
    }
    if (t < BMAX) g_amax[t] = 0ull;                   // reset argmax keys for this replay

    // --- reference bitmask via warp ballot (one label per thread) ---
    if (t < n_total) {
        int b = t / npoint;
        int oid = __ldg(&object_id[b]);
        int jl = t - b * npoint;
        unsigned wbase = (unsigned)(t & ~31);
        if (wbase + 32 <= (unsigned)n_total) {        // full warp, same scene (npoint%32==0)
            unsigned bits = __ballot_sync(0xffffffffu, __ldg(&labels[t]) == oid);
            if ((t & 31) == 0) g_ref_bits[b * NPW + (jl >> 5)] = bits;
        } else {                                      // ragged tail fallback
            if (__ldg(&labels[t]) == oid)
                atomicOr(&g_ref_bits[b * NPW + (jl >> 5)], 1u << (jl & 31u));
        }
    }

    // --- scatter: byte store (idempotent value 1 -> benign races, NO RMW) ---
    if (t < M2) {
        int4 a = __ldcs(&pidx2[t]);                   // two (pid, j) pairs, evict-first
        unsigned j0 = (unsigned)a.y % npu;
        unsigned j1 = (unsigned)a.w % npu;
        g_pc_bytes[(size_t)a.x * STRIDE + j0] = 1;
        g_pc_bytes[(size_t)a.z * STRIDE + j1] = 1;
    }
    if ((M & 1) && t == M2) {                         // odd tail pair
        int2 v = __ldg(&pidx[M - 1]);
        unsigned j = (unsigned)v.y % npu;
        g_pc_bytes[(size_t)v.x * STRIDE + j] = 1;
    }
}

// spread 4 bits into 4 bytes (0x00/0x01 each)
__device__ __forceinline__ unsigned nib2bytes(unsigned nib) {
    return (nib * 0x00204081u) & 0x01010101u;
}

// ---- Kernel B: block-per-proposal byte-count via dp4a + zero-on-read + packed argmax,
//      plus clus_feats_batch writes (block p <-> (scene, slot)).
__global__ void __launch_bounds__(512, 2)
k_reduce(int B, int npoint, int npw, int PTOT, int C,
         const float* __restrict__ feats, float* __restrict__ out) {
    cudaGridDependencySynchronize();                 // PDL guard: wait for k_main's memory
    int p = blockIdx.x;
    int tid = threadIdx.x;

    if (p < PTOT) {
        int b = 0;
        #pragma unroll
        for (int k = 1; k <= BMAX; k++) b += (k <= B && g_offs[k] <= p) ? 1 : 0;
        if (b >= B) b = B - 1;

        uint4* pcq = (uint4*)(g_pc_bytes + (size_t)p * STRIDE);
        const unsigned* __restrict__ refw = g_ref_bits + (size_t)b * NPW;
        int nbq = npoint >> 4;                       // uint4 chunks (16 bytes = 16 points)
        unsigned cnt = 0, its = 0, rs = 0;
        const uint4 z = make_uint4(0u, 0u, 0u, 0u);
        #pragma unroll 2
        for (int q = tid; q < nbq; q += 512) {
            uint4 v = pcq[q];
            unsigned rh = __ldg(&refw[q >> 1]) >> ((q & 1) << 4);  // 16 ref bits
            pcq[q] = z;                              // self-clean for next replay
            cnt = __dp4a(v.x, 0x01010101u, cnt);
            cnt = __dp4a(v.y, 0x01010101u, cnt);
            cnt = __dp4a(v.z, 0x01010101u, cnt);
            cnt = __dp4a(v.w, 0x01010101u, cnt);
            its = __dp4a(v.x & nib2bytes(rh & 0xFu),         0x01010101u, its);
            its = __dp4a(v.y & nib2bytes((rh >> 4) & 0xFu),  0x01010101u, its);
            its = __dp4a(v.z & nib2bytes((rh >> 8) & 0xFu),  0x01010101u, its);
            its = __dp4a(v.w & nib2bytes((rh >> 12) & 0xFu), 0x01010101u, its);
        }
        // byte tail if npoint % 16 != 0
        for (int j = (nbq << 4) + tid; j < npoint; j += 512) {
            unsigned char v = g_pc_bytes[(size_t)p * STRIDE + j];
            g_pc_bytes[(size_t)p * STRIDE + j] = 0;
            if (v) {
                cnt++;
                if ((refw[j >> 5] >> (j & 31)) & 1u) its++;
            }
        }
        // |ref| from the bitmask directly
        for (int w = tid; w < npw; w += 512) rs += __popc(__ldg(&refw[w]));

        cnt = __reduce_add_sync(0xffffffffu, cnt);
        its = __reduce_add_sync(0xffffffffu, its);
        rs  = __reduce_add_sync(0xffffffffu, rs);
        __shared__ unsigned sc[16], si[16], sr[16];
        int warp = tid >> 5;
        if ((tid & 31) == 0) { sc[warp] = cnt; si[warp] = its; sr[warp] = rs; }
        __syncthreads();
        if (tid == 0) {
            unsigned Ct = 0, It = 0, Rt = 0;
            #pragma unroll
            for (int w = 0; w < 16; w++) { Ct += sc[w]; It += si[w]; Rt += sr[w]; }
            float inter = (float)It;
            float uni = (float)Ct + (float)Rt - inter;
            float iou = (uni > 0.0f) ? inter / fmaxf(uni, 1.0f) : 0.0f;
            // packed key: iou (non-negative float, bit-monotone) high 32; tie -> smallest p
            unsigned long long key = ((unsigned long long)__float_as_uint(iou) << 32)
                                   | (unsigned)(0x7fffffff - p);
            atomicMax(&g_amax[b], key);
        }
    }

    // --- clus_feats_batch[b2, slot] = feats[offs[b2]+slot] (zeros past scene end) ---
    int b2 = p / MAXP, slot = p - b2 * MAXP;         // grid covers max(PTOT, B*MAXP)
    if (b2 < B) {
        int lo = g_offs[b2], hi = g_offs[b2 + 1];
        int pp = lo + slot;
        bool valid = (slot < hi - lo);
        float* dst = out + (size_t)(b2 * MAXP + slot) * C;
        const float* src = feats + (size_t)pp * C;
        for (int c = tid; c < C; c += 512)
            dst[c] = valid ? __ldg(&src[c]) : 0.0f;
    }
}

// ---- Kernel C: tiny epilogue — select_feats + scalar outputs.
// Output layout (f32): [B*MAXP*C clus_feats | B*C select_feats | B sel_idx | B+1 offsets | B good]
__global__ void __launch_bounds__(128)
k_final(const float* __restrict__ feats, const int* __restrict__ pes,
        int B, int C, float* __restrict__ out) {
    cudaGridDependencySynchronize();                 // PDL guard: wait for k_reduce's memory
    __shared__ int   s_best[BMAX];
    __shared__ float s_max[BMAX];
    int tid = threadIdx.x;
    if (tid < B) {
        unsigned long long key = g_amax[tid];
        int   p   = 0x7fffffff - (int)(key & 0xffffffffull);
        float iou = __uint_as_float((unsigned)(key >> 32));
        s_best[tid] = (__ldg(&pes[tid]) > 0) ? p : -1;
        s_max[tid]  = iou;
    }
    __syncthreads();
    int sf_off   = B * MAXP * C;
    int spi_off  = sf_off + B * C;
    int offs_off = spi_off + B;
    int good_off = offs_off + B + 1;
    for (int idx = tid; idx < B * C; idx += blockDim.x) {
        int b = idx / C, c = idx - b * C;
        int sel = s_best[b];
        out[sf_off + idx] = (sel >= 0) ? __ldg(&feats[(size_t)sel * C + c]) : 0.0f;
    }
    if (tid < B)  out[spi_off + tid]  = (float)s_best[tid];
    if (tid <= B) out[offs_off + tid] = (float)g_offs[tid];
    if (tid < B)  out[good_off + tid] = ((s_max[tid] > 0.2f) && (__ldg(&pes[tid]) > 0)) ? 1.0f : 0.0f;
}

extern "C" void kernel_launch(void* const* d_in, const int* in_sizes, int n_in,
                              void* d_out, int out_size) {
    const int*   pidx   = (const int*)d_in[0];   // [M,2] int32
    const int*   pes    = (const int*)d_in[1];   // [B] int32
    const int*   labels = (const int*)d_in[2];   // [B*npoint] int32
    const int*   oid    = (const int*)d_in[3];   // [B] int32
    const float* feats  = (const float*)d_in[4]; // [PTOT, C] f32
    float* out = (float*)d_out;

    int M       = in_sizes[0] / 2;
    int B       = in_sizes[1];
    int n_total = in_sizes[2];
    int npoint  = n_total / B;
    int C       = 32;
    int PTOT    = in_sizes[4] / C;
    int npw     = (npoint + 31) / 32;

    int M2 = M / 2;
    int workA = M2 + 1;                       // +1 covers the odd-tail thread
    if (workA < n_total) workA = n_total;
    int gridA = (workA + 255) / 256;
    k_main<<<gridA, 256>>>((const int4*)pidx, (const int2*)pidx, labels, oid, pes,
                           M, M2, B, npoint, n_total, (unsigned)npoint);

    // PDL attribute: allow dependent launch to overlap predecessor drain
    cudaLaunchAttribute attrs[1];
    attrs[0].id = cudaLaunchAttributeProgrammaticStreamSerialization;
    attrs[0].val.programmaticStreamSerializationAllowed = 1;

    int gridB = PTOT > B * MAXP ? PTOT : B * MAXP;
    {
        cudaLaunchConfig_t cfg = {};
        cfg.gridDim  = dim3((unsigned)gridB, 1, 1);
        cfg.blockDim = dim3(512, 1, 1);
        cfg.attrs = attrs; cfg.numAttrs = 1;
        cudaLaunchKernelEx(&cfg, k_reduce, B, npoint, npw, PTOT, C, feats, out);
    }
    {
        cudaLaunchConfig_t cfg = {};
        cfg.gridDim  = dim3(1, 1, 1);
        cfg.blockDim = dim3(128, 1, 1);
        cfg.attrs = attrs; cfg.numAttrs = 1;
        cudaLaunchKernelEx(&cfg, k_final, feats, pes, B, C, out);
    }
}

// round 17
// speedup vs baseline: 2.6798x; 2.6798x over previous
#include <cuda_runtime.h>

#define NPW      2048      // 65536 points / 32 bits (words per proposal row)
#define PTOT_MAX 512
#define BMAX     8
#define MAXP     128

__device__ unsigned           g_pc_bits[PTOT_MAX * NPW]; // 4 MB bitmask; zeroed-on-read by k_reduce
__device__ unsigned           g_ref_bits[BMAX * NPW];    // per-scene reference bitmask (rewritten)
__device__ int                g_offs[BMAX + 1];
__device__ unsigned long long g_amax[BMAX];              // packed (iou_bits<<32 | 0x7fffffff-p)

// ---- Kernel A: scatter (2 pairs/thread, RED.OR) + ref ballot + offsets + amax reset
//      + clus_feats_batch copy (threads t < B*MAXP; per-thread prefix from pes, no race) ----
__global__ void __launch_bounds__(256, 8)
k_main(const int4* __restrict__ pidx2, const int2* __restrict__ pidx,
       const int* __restrict__ labels, const int* __restrict__ object_id,
       const int* __restrict__ pes, const float* __restrict__ feats,
       float* __restrict__ out,
       int M, int M2, int B, int npoint, int n_total, unsigned npu) {
    int t = blockIdx.x * blockDim.x + threadIdx.x;

    if (t == 0) {
        g_offs[0] = 0;
        for (int b = 0; b < B; b++) g_offs[b + 1] = g_offs[b] + __ldg(&pes[b]);
    }
    if (t < BMAX) g_amax[t] = 0ull;                   // reset argmax keys for this replay

    // --- clus_feats_batch[b2, slot] = feats[offs[b2]+slot] (zeros past scene end) ---
    if (t < B * MAXP) {
        int b2 = t / MAXP, slot = t - b2 * MAXP;
        int lo = 0;
        for (int k = 0; k < b2; k++) lo += __ldg(&pes[k]);   // private prefix (B small)
        int cntb = __ldg(&pes[b2]);
        bool valid = (slot < cntb);
        const float4* src = (const float4*)(feats + (size_t)(lo + slot) * 32);
        float4* dst = (float4*)(out + (size_t)t * 32);
        const float4 z4 = make_float4(0.f, 0.f, 0.f, 0.f);
        #pragma unroll
        for (int c = 0; c < 8; c++)
            dst[c] = valid ? __ldg(&src[c]) : z4;
    }

    // --- reference bitmask via warp ballot (one label per thread) ---
    if (t < n_total) {
        int b = t / npoint;
        int oid = __ldg(&object_id[b]);
        int jl = t - b * npoint;
        unsigned wbase = (unsigned)(t & ~31);
        if (wbase + 32 <= (unsigned)n_total) {        // full warp, same scene (npoint%32==0)
            unsigned bits = __ballot_sync(0xffffffffu, __ldg(&labels[t]) == oid);
            if ((t & 31) == 0) g_ref_bits[b * NPW + (jl >> 5)] = bits;
        } else {                                      // ragged tail fallback
            if (__ldg(&labels[t]) == oid)
                atomicOr(&g_ref_bits[b * NPW + (jl >> 5)], 1u << (jl & 31u));
        }
    }

    // --- scatter: set bit (pid, j % npoint); streaming loads protect L2 for the RMW lines ---
    if (t < M2) {
        int4 a = __ldcs(&pidx2[t]);                   // two (pid, j) pairs, evict-first
        unsigned j0 = (unsigned)a.y % npu;
        unsigned j1 = (unsigned)a.w % npu;
        atomicOr(&g_pc_bits[(size_t)a.x * NPW + (j0 >> 5)], 1u << (j0 & 31u));
        atomicOr(&g_pc_bits[(size_t)a.z * NPW + (j1 >> 5)], 1u << (j1 & 31u));
    }
    if ((M & 1) && t == M2) {                         // odd tail pair
        int2 v = __ldg(&pidx[M - 1]);
        unsigned j = (unsigned)v.y % npu;
        atomicOr(&g_pc_bits[(size_t)v.x * NPW + (j >> 5)], 1u << (j & 31u));
    }
}

// ---- Kernel B: block-per-proposal AND-popcount (uint4) + zero-on-read + packed argmax ----
__global__ void __launch_bounds__(256, 8)
k_reduce(int B, int npw) {
    cudaGridDependencySynchronize();                 // PDL guard: wait for k_main's memory
    int p = blockIdx.x;                              // proposal id (grid == PTOT)
    int tid = threadIdx.x;

    int b = 0;
    #pragma unroll
    for (int k = 1; k <= BMAX; k++) b += (k <= B && g_offs[k] <= p) ? 1 : 0;
    if (b >= B) b = B - 1;

    uint4* pcrow = (uint4*)(g_pc_bits + (size_t)p * NPW);
    const uint4* __restrict__ refrow = (const uint4*)(g_ref_bits + (size_t)b * NPW);
    int nq = npw >> 2;                               // uint4 chunks per row (512)
    unsigned cnt = 0, its = 0, rs = 0;
    const uint4 z = make_uint4(0u, 0u, 0u, 0u);
    #pragma unroll 2
    for (int w = tid; w < nq; w += 256) {
        uint4 v = pcrow[w];
        uint4 r = __ldg(&refrow[w]);
        pcrow[w] = z;                                // self-clean for next replay
        cnt += __popc(v.x) + __popc(v.y) + __popc(v.z) + __popc(v.w);
        its += __popc(v.x & r.x) + __popc(v.y & r.y)
             + __popc(v.z & r.z) + __popc(v.w & r.w);
        rs  += __popc(r.x) + __popc(r.y) + __popc(r.z) + __popc(r.w);
    }
    for (int w0 = (nq << 2) + tid; w0 < npw; w0 += 256) {  // word tail (npw % 4)
        unsigned v = g_pc_bits[(size_t)p * NPW + w0];
        unsigned r = g_ref_bits[(size_t)b * NPW + w0];
        g_pc_bits[(size_t)p * NPW + w0] = 0u;
        cnt += __popc(v); its += __popc(v & r); rs += __popc(r);
    }
    cnt = __reduce_add_sync(0xffffffffu, cnt);
    its = __reduce_add_sync(0xffffffffu, its);
    rs  = __reduce_add_sync(0xffffffffu, rs);
    __shared__ unsigned sc[8], si[8], sr[8];
    int warp = tid >> 5;
    if ((tid & 31) == 0) { sc[warp] = cnt; si[warp] = its; sr[warp] = rs; }
    __syncthreads();
    if (tid == 0) {
        unsigned Ct = 0, It = 0, Rt = 0;
        #pragma unroll
        for (int w = 0; w < 8; w++) { Ct += sc[w]; It += si[w]; Rt += sr[w]; }
        float inter = (float)It;
        float uni = (float)Ct + (float)Rt - inter;
        float iou = (uni > 0.0f) ? inter / fmaxf(uni, 1.0f) : 0.0f;
        // packed key: iou (non-negative float, bit-monotone) high 32; tie -> smallest p
        unsigned long long key = ((unsigned long long)__float_as_uint(iou) << 32)
                               | (unsigned)(0x7fffffff - p);
        atomicMax(&g_amax[b], key);
    }
}

// ---- Kernel C: tiny epilogue — select_feats + scalar outputs.
// Output layout (f32): [B*MAXP*C clus_feats | B*C select_feats | B sel_idx | B+1 offsets | B good]
__global__ void __launch_bounds__(128)
k_final(const float* __restrict__ feats, const int* __restrict__ pes,
        int B, int C, float* __restrict__ out) {
    cudaGridDependencySynchronize();                 // PDL guard: wait for k_reduce's memory
    __shared__ int   s_best[BMAX];
    __shared__ float s_max[BMAX];
    int tid = threadIdx.x;
    if (tid < B) {
        unsigned long long key = g_amax[tid];
        int   p   = 0x7fffffff - (int)(key & 0xffffffffull);
        float iou = __uint_as_float((unsigned)(key >> 32));
        s_best[tid] = (__ldg(&pes[tid]) > 0) ? p : -1;
        s_max[tid]  = iou;
    }
    __syncthreads();
    int sf_off   = B * MAXP * C;
    int spi_off  = sf_off + B * C;
    int offs_off = spi_off + B;
    int good_off = offs_off + B + 1;
    for (int idx = tid; idx < B * C; idx += blockDim.x) {
        int b = idx / C, c = idx - b * C;
        int sel = s_best[b];
        out[sf_off + idx] = (sel >= 0) ? __ldg(&feats[(size_t)sel * C + c]) : 0.0f;
    }
    if (tid < B)  out[spi_off + tid]  = (float)s_best[tid];
    if (tid <= B) out[offs_off + tid] = (float)g_offs[tid];
    if (tid < B)  out[good_off + tid] = ((s_max[tid] > 0.2f) && (__ldg(&pes[tid]) > 0)) ? 1.0f : 0.0f;
}

extern "C" void kernel_launch(void* const* d_in, const int* in_sizes, int n_in,
                              void* d_out, int out_size) {
    const int*   pidx   = (const int*)d_in[0];   // [M,2] int32
    const int*   pes    = (const int*)d_in[1];   // [B] int32
    const int*   labels = (const int*)d_in[2];   // [B*npoint] int32
    const int*   oid    = (const int*)d_in[3];   // [B] int32
    const float* feats  = (const float*)d_in[4]; // [PTOT, C] f32
    float* out = (float*)d_out;

    int M       = in_sizes[0] / 2;
    int B       = in_sizes[1];
    int n_total = in_sizes[2];
    int npoint  = n_total / B;
    int C       = 32;
    int PTOT    = in_sizes[4] / C;
    int npw     = (npoint + 31) / 32;

    int M2 = M / 2;
    int workA = M2 + 1;                       // +1 covers the odd-tail thread
    if (workA < n_total) workA = n_total;
    if (workA < B * MAXP) workA = B * MAXP;
    int gridA = (workA + 255) / 256;
    k_main<<<gridA, 256>>>((const int4*)pidx, (const int2*)pidx, labels, oid, pes,
                           feats, out, M, M2, B, npoint, n_total, (unsigned)npoint);

    // PDL attribute: allow dependent launch to overlap predecessor drain
    cudaLaunchAttribute attrs[1];
    attrs[0].id = cudaLaunchAttributeProgrammaticStreamSerialization;
    attrs[0].val.programmaticStreamSerializationAllowed = 1;

    {
        cudaLaunchConfig_t cfg = {};
        cfg.gridDim  = dim3((unsigned)PTOT, 1, 1);
        cfg.blockDim = dim3(256, 1, 1);
        cfg.attrs = attrs; cfg.numAttrs = 1;
        cudaLaunchKernelEx(&cfg, k_reduce, B, npw);
    }
    {
        cudaLaunchConfig_t cfg = {};
        cfg.gridDim  = dim3(1, 1, 1);
        cfg.blockDim = dim3(128, 1, 1);
        cfg.attrs = attrs; cfg.numAttrs = 1;
        cudaLaunchKernelEx(&cfg, k_final, feats, pes, B, C, out);
    }
}